// round 12
// baseline (speedup 1.0000x reference)
#include <cuda_runtime.h>

typedef unsigned long long ull;

#define NROWS   16384
#define DIMP    1024
#define NCLS    10
#define IMG     784

#define REF_BYTES   40960             // dense float[10][1024]
#define RED_BYTES   42240             // 160 rows * 33 * 8
#define SMEM_TOTAL  RED_BYTES         // overlay: max(ref, reduction)

// Normalized reference states, dense (prologue output).
__device__ float g_ref[NCLS * DIMP];

// ---------- f32x2 helpers ----------
__device__ __forceinline__ ull pack2(float lo, float hi) {
    ull r;
    asm("mov.b64 %0, {%1, %2};" : "=l"(r) : "f"(lo), "f"(hi));
    return r;
}
__device__ __forceinline__ void unpack2(ull v, float& lo, float& hi) {
    asm("mov.b64 {%0, %1}, %2;" : "=f"(lo), "=f"(hi) : "l"(v));
}
__device__ __forceinline__ void fma2(ull& acc, ull a, ull b) {
    asm("fma.rn.f32x2 %0, %1, %2, %0;" : "+l"(acc) : "l"(a), "l"(b));
}
__device__ __forceinline__ void add2(ull& acc, ull a) {
    asm("add.rn.f32x2 %0, %1, %0;" : "+l"(acc) : "l"(a));
}

#define COMP(v, j) ((j) == 0 ? (v).x : ((j) == 1 ? (v).y : ((j) == 2 ? (v).z : (v).w)))

// ---------- prologue: pad + L2-normalize canon -> g_ref ----------
__global__ void ref_norm_kernel(const float* __restrict__ canon) {
    __shared__ float buf[DIMP];
    __shared__ float wsum[8];
    __shared__ float inv;
    int c = blockIdx.x, t = threadIdx.x;
    float ps = 0.f;
    for (int i = t; i < DIMP; i += 256) {
        float v = (i < IMG) ? canon[c * IMG + i] : 0.f;
        buf[i] = v;
        ps += v * v;
    }
    #pragma unroll
    for (int o = 16; o; o >>= 1) ps += __shfl_xor_sync(0xFFFFFFFFu, ps, o);
    if ((t & 31) == 0) wsum[t >> 5] = ps;
    __syncthreads();
    if (t == 0) {
        float s = 0.f;
        #pragma unroll
        for (int i = 0; i < 8; i++) s += wsum[i];
        inv = 1.0f / sqrtf(s);
    }
    __syncthreads();
    float iv = inv;
    for (int i = t; i < DIMP; i += 256)
        g_ref[c * DIMP + i] = buf[i] * iv;
}

// ---------- main kernel ----------
// 256 threads = 8 warps, 2 rows/warp (row-pair f32x2 packing) -> 16 rows/block.
// __launch_bounds__(256,3): 3 blocks/SM = 24 warps/SM.
// ref LDS amplification = 2.5x (vs 5x at 1 row/warp) -> LDS floor ~10us, DRAM binds.
__global__ __launch_bounds__(256, 3) void swap_test_kernel(
    const float* __restrict__ zre, const float* __restrict__ zim,
    float* __restrict__ out) {

    extern __shared__ __align__(16) char smem[];
    const int tid  = threadIdx.x;
    const int lane = tid & 31;
    const int w    = tid >> 5;
    const int rowBase0 = blockIdx.x * 16;

    // per-warp z sources: rows 2w, 2w+1, re & im; issue tile-0/1 LDGs early
    const float4* zrb = (const float4*)(zre + (size_t)(rowBase0 + 2 * w) * DIMP);
    const float4* zib = (const float4*)(zim + (size_t)(rowBase0 + 2 * w) * DIMP);

    float4 c0 = zrb[lane],      c1 = zrb[256 + lane];   // row0/1 re, tile 0
    float4 c2 = zib[lane],      c3 = zib[256 + lane];   // row0/1 im, tile 0

    // stage dense ref into smem (float4 copies, conflict-free)
    {
        const float4* g4 = (const float4*)g_ref;
        float4* s4 = (float4*)smem;
        for (int i = tid; i < NCLS * DIMP / 4; i += 256) s4[i] = g4[i];
    }
    __syncthreads();

    // acc: A[2c] = (s_re[row0,c], s_re[row1,c]); A[2c+1] = im counterpart
    ull A[20];
    #pragma unroll
    for (int i = 0; i < 20; i++) A[i] = 0ull;

    const float4* rf4 = (const float4*)smem;

    #pragma unroll
    for (int k = 0; k < 8; k++) {
        float4 n0, n1, n2, n3;
        if (k < 7) {
            const int di = (k + 1) * 32 + lane;
            n0 = zrb[di]; n1 = zrb[256 + di];
            n2 = zib[di]; n3 = zib[256 + di];
        }

        // pack row pairs once per k (8 ull, replaces the consumed tiles)
        ull pre[4], pim[4];
        #pragma unroll
        for (int j = 0; j < 4; j++) {
            pre[j] = pack2(COMP(c0, j), COMP(c1, j));
            pim[j] = pack2(COMP(c2, j), COMP(c3, j));
        }

        const float4* rk = rf4 + k * 32 + lane;
        #pragma unroll
        for (int c = 0; c < NCLS; c++) {
            float4 f = rk[c * 256];
            ull fd;
            fd = pack2(f.x, f.x);
            fma2(A[2 * c], pre[0], fd); fma2(A[2 * c + 1], pim[0], fd);
            fd = pack2(f.y, f.y);
            fma2(A[2 * c], pre[1], fd); fma2(A[2 * c + 1], pim[1], fd);
            fd = pack2(f.z, f.z);
            fma2(A[2 * c], pre[2], fd); fma2(A[2 * c + 1], pim[2], fd);
            fd = pack2(f.w, f.w);
            fma2(A[2 * c], pre[3], fd); fma2(A[2 * c + 1], pim[3], fd);
        }

        if (k < 7) { c0 = n0; c1 = n1; c2 = n2; c3 = n3; }
    }

    __syncthreads();   // all warps done with staged ref -> overlay reduction buffer

    // lane partials: 8 warps x 20 ull rows, stride 33 (conflict-free STS.64)
    ull* red = (ull*)smem;
    #pragma unroll
    for (int i = 0; i < 20; i++)
        red[(w * 20 + i) * 33 + lane] = A[i];
    __syncthreads();

    // 80 tasks: (warp w2, class c) -> rows 2w2, 2w2+1 for class c
    if (tid < 80) {
        const int w2 = tid / 10;
        const int c  = tid % 10;
        const int mRe = w2 * 20 + c * 2;
        ull sre = 0ull, sim = 0ull;
        #pragma unroll
        for (int x = 0; x < 32; x++) {
            add2(sre, red[mRe * 33 + x]);
            add2(sim, red[(mRe + 1) * 33 + x]);
        }
        float reL, reH, imL, imH;
        unpack2(sre, reL, reH);
        unpack2(sim, imL, imH);
        const size_t row = (size_t)rowBase0 + (size_t)w2 * 2;
        out[row * NCLS + c]       = reL * reL + imL * imL;
        out[(row + 1) * NCLS + c] = reH * reH + imH * imH;
    }
}

extern "C" void kernel_launch(void* const* d_in, const int* in_sizes, int n_in,
                              void* d_out, int out_size) {
    const float* zre   = (const float*)d_in[0];
    const float* zim   = (const float*)d_in[1];
    const float* canon = (const float*)d_in[2];
    float* out = (float*)d_out;

    cudaFuncSetAttribute(swap_test_kernel,
                         cudaFuncAttributeMaxDynamicSharedMemorySize, SMEM_TOTAL);

    ref_norm_kernel<<<NCLS, 256>>>(canon);
    swap_test_kernel<<<NROWS / 16, 256, SMEM_TOTAL>>>(zre, zim, out);
}

// round 13
// speedup vs baseline: 1.4936x; 1.4936x over previous
#include <cuda_runtime.h>

typedef unsigned long long ull;
typedef unsigned int u32;

#define NROWS   16384
#define DIMP    1024
#define NCLS    10
#define IMG     784
#define QSTRIDE 22                    // ull per d-quad group: 20 data + 2 pad (176 B)

#define REF_BYTES   45056             // 256 groups * 176 B
#define NSTAGE      3
#define WSTAGE      1024              // per-warp stage: 1 row * 2 arrays * 512 B
#define Z_OFF       REF_BYTES
#define NWARP       16
#define SMEM_TOTAL  (Z_OFF + NWARP * NSTAGE * WSTAGE)   // 45056 + 49152 = 94208

#define NTILE   7                     // d >= 896 is all-zero ref; tile 6 only d<784 real

// Packed reference pairs (prologue output), dense layout:
// g_refp[(d>>2)*20 + p*4 + (d&3)] = ( ref[2p][d], ref[2p+1][d] )
__device__ ull g_refp[256 * 20];

// ---------- f32x2 helpers ----------
__device__ __forceinline__ ull pack2(float lo, float hi) {
    ull r;
    asm("mov.b64 %0, {%1, %2};" : "=l"(r) : "f"(lo), "f"(hi));
    return r;
}
__device__ __forceinline__ void unpack2(ull v, float& lo, float& hi) {
    asm("mov.b64 {%0, %1}, %2;" : "=f"(lo), "=f"(hi) : "l"(v));
}
__device__ __forceinline__ void fma2(ull& acc, ull a, ull b) {
    asm("fma.rn.f32x2 %0, %1, %2, %0;" : "+l"(acc) : "l"(a), "l"(b));
}
__device__ __forceinline__ void add2(ull& acc, ull a) {
    asm("add.rn.f32x2 %0, %1, %0;" : "+l"(acc) : "l"(a));
}

// ---------- cp.async helpers (per-warp private pipeline, no barriers) ----------
__device__ __forceinline__ u32 smem_u32(const void* p) {
    u32 a;
    asm("{ .reg .u64 t; cvta.to.shared.u64 t, %1; cvt.u32.u64 %0, t; }" : "=r"(a) : "l"(p));
    return a;
}
__device__ __forceinline__ void cp16(u32 dst, const void* src) {
    asm volatile("cp.async.cg.shared.global [%0], [%1], 16;" :: "r"(dst), "l"(src) : "memory");
}
__device__ __forceinline__ void cp_commit() {
    asm volatile("cp.async.commit_group;" ::: "memory");
}
__device__ __forceinline__ void cp_wait2() {
    asm volatile("cp.async.wait_group 2;" ::: "memory");
}

// ---------- prologue: block p normalizes classes 2p, 2p+1, writes packed pairs ----------
__global__ void ref_pack_kernel(const float* __restrict__ canon) {
    __shared__ float v0[DIMP], v1[DIMP];
    __shared__ float wred[16];
    __shared__ float invs[2];
    const int p = blockIdx.x, t = threadIdx.x;
    const float* c0 = canon + (2 * p) * IMG;
    const float* c1 = canon + (2 * p + 1) * IMG;
    float s0 = 0.f, s1 = 0.f;
    for (int i = t; i < DIMP; i += 256) {
        float a = (i < IMG) ? c0[i] : 0.f;
        float b = (i < IMG) ? c1[i] : 0.f;
        v0[i] = a; v1[i] = b;
        s0 += a * a; s1 += b * b;
    }
    #pragma unroll
    for (int o = 16; o; o >>= 1) {
        s0 += __shfl_xor_sync(0xFFFFFFFFu, s0, o);
        s1 += __shfl_xor_sync(0xFFFFFFFFu, s1, o);
    }
    if ((t & 31) == 0) { wred[t >> 5] = s0; wred[8 + (t >> 5)] = s1; }
    __syncthreads();
    if (t == 0) {
        float a = 0.f, b = 0.f;
        #pragma unroll
        for (int i = 0; i < 8; i++) { a += wred[i]; b += wred[8 + i]; }
        invs[0] = 1.0f / sqrtf(a);
        invs[1] = 1.0f / sqrtf(b);
    }
    __syncthreads();
    const float i0 = invs[0], i1 = invs[1];
    for (int d = t; d < DIMP; d += 256)
        g_refp[(d >> 2) * 20 + p * 4 + (d & 3)] = pack2(v0[d] * i0, v1[d] * i1);
}

// ---------- main kernel ----------
// 512 threads = 16 warps, 1 row/warp -> 16 rows/block, grid = 1024.
// 2 blocks/SM -> 32 warps/SM. Per-warp private 3-stage cp.async ring, zero
// cross-warp sync in the loop.
// ZERO-PAD EXPLOIT: ref[c][d] = 0 for d >= 784 -> k-tile 7 skipped entirely;
// tile 6 z-loads predicated to lanes 0-3 (d < 784+16). Lanes 4-31 read stale
// (finite) stage data that multiplies zero ref -> exact result, 23% less DRAM.
__global__ __launch_bounds__(512, 2) void swap_test_kernel(
    const float* __restrict__ zre, const float* __restrict__ zim,
    float* __restrict__ out) {

    extern __shared__ __align__(16) char smem[];
    const u32 sbase = smem_u32(smem);
    const int tid  = threadIdx.x;
    const int lane = tid & 31;
    const int w    = tid >> 5;
    const int rowBase0 = blockIdx.x * 16;

    // stage packed ref into smem (176 B groups: 20 data ull + 2 pad)
    {
        ull* s = (ull*)smem;
        for (int i = tid; i < 5120; i += 512) {
            const int q = i / 20;
            const int r = i - q * 20;
            s[q * QSTRIDE + r] = g_refp[i];
        }
    }

    // per-warp z sources (1 row x {re,im})
    const float* zr0 = zre + (size_t)(rowBase0 + w) * DIMP;
    const float* zi0 = zim + (size_t)(rowBase0 + w) * DIMP;
    const u32 zring = sbase + Z_OFF + (u32)w * (NSTAGE * WSTAGE) + (u32)lane * 16;
    const int lo4 = lane * 4;

    // prime stages 0,1 (tiles 0,1)
    #pragma unroll
    for (int kk = 0; kk < 2; kk++) {
        const u32 d = zring + kk * WSTAGE;
        cp16(d,       zr0 + kk * 128 + lo4);
        cp16(d + 512, zi0 + kk * 128 + lo4);
        cp_commit();
    }

    __syncthreads();   // ref staging visible to all warps

    ull A[10];
    #pragma unroll
    for (int i = 0; i < 10; i++) A[i] = 0ull;

    const char* rp = smem + (size_t)lane * (QSTRIDE * 8);

    #pragma unroll
    for (int k = 0; k < NTILE; k++) {
        // issue tile k+2 into stage (k+2)%3 (distance-2 prefetch)
        if (k < NTILE - 2) {
            const int kk = k + 2;
            const u32 d = zring + (kk % NSTAGE) * WSTAGE;
            if (kk < 6) {
                cp16(d,       zr0 + kk * 128 + lo4);
                cp16(d + 512, zi0 + kk * 128 + lo4);
            } else if (lane < 4) {
                // tile 6: only d = 768..783 is live (ref zero beyond 784)
                cp16(d,       zr0 + 6 * 128 + lo4);
                cp16(d + 512, zi0 + 6 * 128 + lo4);
            }
        }
        cp_commit();       // always commit (possibly empty) to keep count invariant
        cp_wait2();        // tile k's group is now complete

        const char* zb = smem + Z_OFF + (size_t)w * (NSTAGE * WSTAGE)
                              + (size_t)(k % NSTAGE) * WSTAGE + (size_t)lane * 16;
        float4 c0 = *(const float4*)(zb);          // re
        float4 c2 = *(const float4*)(zb + 512);    // im

        // duplicate z scalars into f32x2 operands (reused across 5 class-pairs)
        ull d0[4], d2[4];
        d0[0] = pack2(c0.x, c0.x); d0[1] = pack2(c0.y, c0.y);
        d0[2] = pack2(c0.z, c0.z); d0[3] = pack2(c0.w, c0.w);
        d2[0] = pack2(c2.x, c2.x); d2[1] = pack2(c2.y, c2.y);
        d2[2] = pack2(c2.z, c2.z); d2[3] = pack2(c2.w, c2.w);

        const char* rk = rp + k * (32 * QSTRIDE * 8);
        #pragma unroll
        for (int p = 0; p < 5; p++) {
            ulonglong2 fa = *(const ulonglong2*)(rk + p * 32);
            ulonglong2 fb = *(const ulonglong2*)(rk + p * 32 + 16);
            fma2(A[p * 2 + 0], d0[0], fa.x); fma2(A[p * 2 + 0], d0[1], fa.y);
            fma2(A[p * 2 + 0], d0[2], fb.x); fma2(A[p * 2 + 0], d0[3], fb.y);
            fma2(A[p * 2 + 1], d2[0], fa.x); fma2(A[p * 2 + 1], d2[1], fa.y);
            fma2(A[p * 2 + 1], d2[2], fb.x); fma2(A[p * 2 + 1], d2[3], fb.y);
        }
    }

    __syncthreads();   // all warps done with staged ref -> overlay reduction buffer

    // lane partials: 16 warps x 10 ull rows, stride 33 (conflict-free STS.64)
    // 160 * 33 * 8 = 42,240 B < REF_BYTES, fits in the overlaid ref area.
    ull* red = (ull*)smem;
    #pragma unroll
    for (int i = 0; i < 10; i++)
        red[(w * 10 + i) * 33 + lane] = A[i];
    __syncthreads();

    // 80 tasks: (warp w2, class-pair p) -> 2 outputs (classes 2p, 2p+1) for one row
    if (tid < 80) {
        const int w2 = tid / 5;
        const int p  = tid % 5;
        const int mRe = w2 * 10 + p * 2;
        ull sre = 0ull, sim = 0ull;
        #pragma unroll
        for (int x = 0; x < 32; x++) {
            add2(sre, red[mRe * 33 + x]);
            add2(sim, red[(mRe + 1) * 33 + x]);
        }
        float reL, reH, imL, imH;
        unpack2(sre, reL, reH);
        unpack2(sim, imL, imH);
        const size_t row = (size_t)rowBase0 + (size_t)w2;
        out[row * NCLS + 2 * p]     = reL * reL + imL * imL;
        out[row * NCLS + 2 * p + 1] = reH * reH + imH * imH;
    }
}

extern "C" void kernel_launch(void* const* d_in, const int* in_sizes, int n_in,
                              void* d_out, int out_size) {
    const float* zre   = (const float*)d_in[0];
    const float* zim   = (const float*)d_in[1];
    const float* canon = (const float*)d_in[2];
    float* out = (float*)d_out;

    cudaFuncSetAttribute(swap_test_kernel,
                         cudaFuncAttributeMaxDynamicSharedMemorySize, SMEM_TOTAL);

    ref_pack_kernel<<<NCLS / 2, 256>>>(canon);
    swap_test_kernel<<<NROWS / 16, 512, SMEM_TOTAL>>>(zre, zim, out);
}

// round 15
// speedup vs baseline: 1.6006x; 1.0716x over previous
#include <cuda_runtime.h>

typedef unsigned long long ull;

#define NROWS   16384
#define DIMP    1024
#define NCLS    10
#define IMG     784
#define QSTRIDE 22              // ull per d-quad group in smem: 20 data + 2 pad (176 B)

#define NTILE   7               // ref[d>=896]==0 -> tile 7 skipped; tile 6 only d<784 live

// Packed reference pairs (prologue output), dense layout:
// g_refp[(d>>2)*20 + p*4 + (d&3)] = ( ref[2p][d], ref[2p+1][d] )
__device__ ull g_refp[256 * 20];

// ---------- f32x2 helpers ----------
__device__ __forceinline__ ull pack2(float lo, float hi) {
    ull r;
    asm("mov.b64 %0, {%1, %2};" : "=l"(r) : "f"(lo), "f"(hi));
    return r;
}
__device__ __forceinline__ void unpack2(ull v, float& lo, float& hi) {
    asm("mov.b64 {%0, %1}, %2;" : "=f"(lo), "=f"(hi) : "l"(v));
}
__device__ __forceinline__ void fma2(ull& acc, ull a, ull b) {
    asm("fma.rn.f32x2 %0, %1, %2, %0;" : "+l"(acc) : "l"(a), "l"(b));
}
__device__ __forceinline__ void add2(ull& acc, ull a) {
    asm("add.rn.f32x2 %0, %1, %0;" : "+l"(acc) : "l"(a));
}

// ---------- prologue: block p normalizes classes 2p, 2p+1 and writes packed pairs ----------
__global__ void ref_pack_kernel(const float* __restrict__ canon) {
    __shared__ float v0[DIMP], v1[DIMP];
    __shared__ float wred[16];
    __shared__ float invs[2];
    const int p = blockIdx.x, t = threadIdx.x;
    const float* c0 = canon + (2 * p) * IMG;
    const float* c1 = canon + (2 * p + 1) * IMG;
    float s0 = 0.f, s1 = 0.f;
    for (int i = t; i < DIMP; i += 256) {
        float a = (i < IMG) ? c0[i] : 0.f;
        float b = (i < IMG) ? c1[i] : 0.f;
        v0[i] = a; v1[i] = b;
        s0 += a * a; s1 += b * b;
    }
    #pragma unroll
    for (int o = 16; o; o >>= 1) {
        s0 += __shfl_xor_sync(0xFFFFFFFFu, s0, o);
        s1 += __shfl_xor_sync(0xFFFFFFFFu, s1, o);
    }
    if ((t & 31) == 0) { wred[t >> 5] = s0; wred[8 + (t >> 5)] = s1; }
    __syncthreads();
    if (t == 0) {
        float a = 0.f, b = 0.f;
        #pragma unroll
        for (int i = 0; i < 8; i++) { a += wred[i]; b += wred[8 + i]; }
        invs[0] = 1.0f / sqrtf(a);
        invs[1] = 1.0f / sqrtf(b);
    }
    __syncthreads();
    const float i0 = invs[0], i1 = invs[1];
    for (int d = t; d < DIMP; d += 256)
        g_refp[(d >> 2) * 20 + p * 4 + (d & 3)] = pack2(v0[d] * i0, v1[d] * i1);
}

// ---------- main kernel ----------
// 256 threads = 8 warps, 2 rows/warp -> 16 rows/block, grid = 1024.
// R4's proven structure (best ref-LDS amplification per register) combined with
// R13's validated zero-pad exploit:
//   - ref[c][d] = 0 for d >= 784  -> k-tile 7 skipped entirely (12.5% less work)
//   - tile 6 z-loads predicated to lanes 0-3 (d < 800); lanes 4-31 keep stale
//     finite register values that multiply ref == 0 -> exact result.
// Total z DRAM: 134 MB -> 103 MB.
__global__ __launch_bounds__(256, 2) void swap_test_kernel(
    const float* __restrict__ zre, const float* __restrict__ zim,
    float* __restrict__ out) {

    __shared__ __align__(16) ull sm[256 * QSTRIDE];   // 45056 B

    const int tid = threadIdx.x;

    // stage packed ref into smem, inserting 16 B pad per 160 B data group
    {
        const float4* g4 = (const float4*)g_refp;
        for (int c = tid; c < 2560; c += 256) {
            const int q = c / 10;
            const int r = c - q * 10;
            *((float4*)((char*)sm + q * (QSTRIDE * 8) + r * 16)) = g4[c];
        }
    }
    __syncthreads();

    const int lane = tid & 31;
    const int w    = tid >> 5;
    const size_t rowBase = (size_t)blockIdx.x * 16 + (size_t)w * 2;
    const float4* zr = (const float4*)zre + rowBase * 256;
    const float4* zi = (const float4*)zim + rowBase * 256;
    const char* rp = (const char*)sm + (size_t)lane * (QSTRIDE * 8);

    // acc A[p*4 + arr*2 + row]: f32x2 holds (class 2p, class 2p+1) partial sums
    ull A[20];
    #pragma unroll
    for (int i = 0; i < 20; i++) A[i] = 0ull;

    // tile 0
    float4 c0 = zr[lane],       c1 = zr[256 + lane];
    float4 c2 = zi[lane],       c3 = zi[256 + lane];

    #pragma unroll
    for (int k = 0; k < NTILE; k++) {
        float4 n0, n1, n2, n3;
        if (k < NTILE - 1) {
            const int kk = k + 1;
            if (kk < 6 || lane < 4) {         // tile 6: only d=768..783 live
                const int di = kk * 32 + lane;
                n0 = zr[di]; n1 = zr[256 + di];
                n2 = zi[di]; n3 = zi[256 + di];
            } else {                           // stale-but-finite is fine (ref==0)
                n0 = c0; n1 = c1; n2 = c2; n3 = c3;
            }
        }

        // duplicate z scalars into f32x2 operands (reused across 5 class-pairs)
        ull d0[4], d1[4], d2[4], d3[4];
        d0[0] = pack2(c0.x, c0.x); d0[1] = pack2(c0.y, c0.y);
        d0[2] = pack2(c0.z, c0.z); d0[3] = pack2(c0.w, c0.w);
        d1[0] = pack2(c1.x, c1.x); d1[1] = pack2(c1.y, c1.y);
        d1[2] = pack2(c1.z, c1.z); d1[3] = pack2(c1.w, c1.w);
        d2[0] = pack2(c2.x, c2.x); d2[1] = pack2(c2.y, c2.y);
        d2[2] = pack2(c2.z, c2.z); d2[3] = pack2(c2.w, c2.w);
        d3[0] = pack2(c3.x, c3.x); d3[1] = pack2(c3.y, c3.y);
        d3[2] = pack2(c3.z, c3.z); d3[3] = pack2(c3.w, c3.w);

        const char* rk = rp + k * (32 * QSTRIDE * 8);
        #pragma unroll
        for (int p = 0; p < 5; p++) {
            ulonglong2 fa = *(const ulonglong2*)(rk + p * 32);
            ulonglong2 fb = *(const ulonglong2*)(rk + p * 32 + 16);
            // row0 re
            fma2(A[p * 4 + 0], d0[0], fa.x); fma2(A[p * 4 + 0], d0[1], fa.y);
            fma2(A[p * 4 + 0], d0[2], fb.x); fma2(A[p * 4 + 0], d0[3], fb.y);
            // row0 im
            fma2(A[p * 4 + 1], d2[0], fa.x); fma2(A[p * 4 + 1], d2[1], fa.y);
            fma2(A[p * 4 + 1], d2[2], fb.x); fma2(A[p * 4 + 1], d2[3], fb.y);
            // row1 re
            fma2(A[p * 4 + 2], d1[0], fa.x); fma2(A[p * 4 + 2], d1[1], fa.y);
            fma2(A[p * 4 + 2], d1[2], fb.x); fma2(A[p * 4 + 2], d1[3], fb.y);
            // row1 im
            fma2(A[p * 4 + 3], d3[0], fa.x); fma2(A[p * 4 + 3], d3[1], fa.y);
            fma2(A[p * 4 + 3], d3[2], fb.x); fma2(A[p * 4 + 3], d3[3], fb.y);
        }

        if (k < NTILE - 1) { c0 = n0; c1 = n1; c2 = n2; c3 = n3; }
    }

    __syncthreads();   // all warps done with staged ref -> overlay reduction buffer

    // lane partials: 8 warps x 20 ull rows, stride 33 (bank-conflict-free STS.64)
    ull* red = sm;
    #pragma unroll
    for (int i = 0; i < 20; i++)
        red[(w * 20 + i) * 33 + lane] = A[i];
    __syncthreads();

    // 80 tasks: (warp w2, class-pair p, row j) -> 2 outputs each
    if (tid < 80) {
        const int w2 = tid / 10;
        const int q  = tid % 10;
        const int p  = q >> 1;
        const int j  = q & 1;
        const int mRe = w2 * 20 + p * 4 + j * 2;
        ull sre = 0ull, sim = 0ull;
        #pragma unroll
        for (int x = 0; x < 32; x++) {
            add2(sre, red[mRe * 33 + x]);
            add2(sim, red[(mRe + 1) * 33 + x]);
        }
        float reL, reH, imL, imH;
        unpack2(sre, reL, reH);
        unpack2(sim, imL, imH);
        const size_t row = (size_t)blockIdx.x * 16 + (size_t)w2 * 2 + (size_t)j;
        out[row * NCLS + 2 * p]     = reL * reL + imL * imL;
        out[row * NCLS + 2 * p + 1] = reH * reH + imH * imH;
    }
}

extern "C" void kernel_launch(void* const* d_in, const int* in_sizes, int n_in,
                              void* d_out, int out_size) {
    const float* zre   = (const float*)d_in[0];
    const float* zim   = (const float*)d_in[1];
    const float* canon = (const float*)d_in[2];
    float* out = (float*)d_out;

    ref_pack_kernel<<<NCLS / 2, 256>>>(canon);
    swap_test_kernel<<<NROWS / 16, 256>>>(zre, zim, out);
}

// round 16
// speedup vs baseline: 1.7731x; 1.1078x over previous
#include <cuda_runtime.h>

typedef unsigned long long ull;
typedef unsigned int u32;

#define NROWS   16384
#define DIMP    1024
#define NCLS    10
#define IMG     784

#define NTILE   7                 // ref[d>=896]==0 -> tile 7 skipped; tile 6 only d<784 live
#define NGROUP  224               // 7 tiles * 32 d-quad groups staged (k < 7 only)
#define REF_BYTES (NGROUP * 176)  // 39424
#define NSTAGE  2
#define WSTAGE  2048              // per-warp stage: 2 rows * 2 arrays * 512 B
#define Z_OFF   REF_BYTES
#define SMEM_TOTAL (Z_OFF + 8 * NSTAGE * WSTAGE)   // 39424 + 32768 = 72192

// Packed reference pairs (prologue output), dense layout:
// g_refp[(d>>2)*20 + p*4 + (d&3)] = ( ref[2p][d], ref[2p+1][d] )
__device__ ull g_refp[256 * 20];

// ---------- f32x2 helpers ----------
__device__ __forceinline__ ull pack2(float lo, float hi) {
    ull r;
    asm("mov.b64 %0, {%1, %2};" : "=l"(r) : "f"(lo), "f"(hi));
    return r;
}
__device__ __forceinline__ void unpack2(ull v, float& lo, float& hi) {
    asm("mov.b64 {%0, %1}, %2;" : "=f"(lo), "=f"(hi) : "l"(v));
}
__device__ __forceinline__ void fma2(ull& acc, ull a, ull b) {
    asm("fma.rn.f32x2 %0, %1, %2, %0;" : "+l"(acc) : "l"(a), "l"(b));
}
__device__ __forceinline__ void add2(ull& acc, ull a) {
    asm("add.rn.f32x2 %0, %1, %0;" : "+l"(acc) : "l"(a));
}

// ---------- cp.async helpers (per-warp private pipeline, no barriers) ----------
__device__ __forceinline__ u32 smem_u32(const void* p) {
    u32 a;
    asm("{ .reg .u64 t; cvta.to.shared.u64 t, %1; cvt.u32.u64 %0, t; }" : "=r"(a) : "l"(p));
    return a;
}
__device__ __forceinline__ void cp16(u32 dst, const void* src) {
    asm volatile("cp.async.cg.shared.global [%0], [%1], 16;" :: "r"(dst), "l"(src) : "memory");
}
__device__ __forceinline__ void cp_commit() {
    asm volatile("cp.async.commit_group;" ::: "memory");
}
__device__ __forceinline__ void cp_wait1() {
    asm volatile("cp.async.wait_group 1;" ::: "memory");
}

// ---------- prologue: block p normalizes classes 2p, 2p+1 and writes packed pairs ----------
__global__ void ref_pack_kernel(const float* __restrict__ canon) {
    __shared__ float v0[DIMP], v1[DIMP];
    __shared__ float wred[16];
    __shared__ float invs[2];
    const int p = blockIdx.x, t = threadIdx.x;
    const float* c0 = canon + (2 * p) * IMG;
    const float* c1 = canon + (2 * p + 1) * IMG;
    float s0 = 0.f, s1 = 0.f;
    for (int i = t; i < DIMP; i += 256) {
        float a = (i < IMG) ? c0[i] : 0.f;
        float b = (i < IMG) ? c1[i] : 0.f;
        v0[i] = a; v1[i] = b;
        s0 += a * a; s1 += b * b;
    }
    #pragma unroll
    for (int o = 16; o; o >>= 1) {
        s0 += __shfl_xor_sync(0xFFFFFFFFu, s0, o);
        s1 += __shfl_xor_sync(0xFFFFFFFFu, s1, o);
    }
    if ((t & 31) == 0) { wred[t >> 5] = s0; wred[8 + (t >> 5)] = s1; }
    __syncthreads();
    if (t == 0) {
        float a = 0.f, b = 0.f;
        #pragma unroll
        for (int i = 0; i < 8; i++) { a += wred[i]; b += wred[8 + i]; }
        invs[0] = 1.0f / sqrtf(a);
        invs[1] = 1.0f / sqrtf(b);
    }
    __syncthreads();
    const float i0 = invs[0], i1 = invs[1];
    for (int d = t; d < DIMP; d += 256)
        g_refp[(d >> 2) * 20 + p * 4 + (d & 3)] = pack2(v0[d] * i0, v1[d] * i1);
}

// ---------- main kernel ----------
// 256 threads = 8 warps, 2 rows/warp, grid 1024; __launch_bounds__(256,3):
// 24 warps/SM (the R=2 + occupancy combination, enabled by a register diet):
//  - z via per-warp private 2-stage cp.async ring, distance-1 (no tile regs)
//  - half-split dup packing: only 8 dup ULLs live (16 regs, not 32)
//  - zero-pad exploit: 7 tiles, tile-6 cp predicated to lanes 0-3
// Zero cross-warp synchronization inside the main loop.
__global__ __launch_bounds__(256, 3) void swap_test_kernel(
    const float* __restrict__ zre, const float* __restrict__ zim,
    float* __restrict__ out) {

    extern __shared__ __align__(16) char smem[];
    const u32 sbase = smem_u32(smem);
    const int tid  = threadIdx.x;
    const int lane = tid & 31;
    const int w    = tid >> 5;
    const int rowBase0 = blockIdx.x * 16;

    // stage packed ref (7 tiles = 224 groups of 176 B: 160 B data + 16 B pad)
    {
        const float4* g4 = (const float4*)g_refp;
        for (int c = tid; c < NGROUP * 10; c += 256) {
            const int q = c / 10;
            const int r = c - q * 10;
            *((float4*)(smem + q * 176 + r * 16)) = g4[c];
        }
    }

    // z sources: rows 2w, 2w+1 for re & im; lane covers bytes [lane*16, lane*16+16)
    const char* zrsrc = (const char*)(zre + (size_t)(rowBase0 + 2 * w) * DIMP) + lane * 16;
    const char* zisrc = (const char*)(zim + (size_t)(rowBase0 + 2 * w) * DIMP) + lane * 16;
    const u32 zst = sbase + Z_OFF + (u32)w * (NSTAGE * WSTAGE) + (u32)lane * 16;

    // prime tile 0 -> stage 0
    cp16(zst,        zrsrc);
    cp16(zst + 512,  zrsrc + 4096);
    cp16(zst + 1024, zisrc);
    cp16(zst + 1536, zisrc + 4096);
    cp_commit();

    __syncthreads();   // ref staging visible

    // acc A[p*4 + arr*2 + row]: f32x2 holds (class 2p, class 2p+1) partial sums
    ull A[20];
    #pragma unroll
    for (int i = 0; i < 20; i++) A[i] = 0ull;

    const char* rp = smem + (size_t)lane * 176;

    #pragma unroll
    for (int k = 0; k < NTILE; k++) {
        // distance-1 prefetch: tile k+1 into the other stage
        if (k < NTILE - 1) {
            const int kk = k + 1;
            const u32 d = zst + (kk & 1) * WSTAGE;
            if (kk < 6 || lane < 4) {      // tile 6: only d = 768..783 live
                cp16(d,        zrsrc + kk * 512);
                cp16(d + 512,  zrsrc + kk * 512 + 4096);
                cp16(d + 1024, zisrc + kk * 512);
                cp16(d + 1536, zisrc + kk * 512 + 4096);
            }
        }
        cp_commit();      // always commit (possibly empty) to keep count invariant
        cp_wait1();       // tile k's group complete (<=1 outstanding: tile k+1)

        const char* zb = smem + Z_OFF + (size_t)w * (NSTAGE * WSTAGE)
                              + (size_t)(k & 1) * WSTAGE + (size_t)lane * 16;
        const char* rk = rp + k * (32 * 176);

        #pragma unroll
        for (int h = 0; h < 2; h++) {      // component halves {x,y} then {z,w}
            float2 z0 = *(const float2*)(zb +        h * 8);   // row0 re
            float2 z1 = *(const float2*)(zb +  512 + h * 8);   // row1 re
            float2 z2 = *(const float2*)(zb + 1024 + h * 8);   // row0 im
            float2 z3 = *(const float2*)(zb + 1536 + h * 8);   // row1 im

            ull d0a = pack2(z0.x, z0.x), d0b = pack2(z0.y, z0.y);
            ull d1a = pack2(z1.x, z1.x), d1b = pack2(z1.y, z1.y);
            ull d2a = pack2(z2.x, z2.x), d2b = pack2(z2.y, z2.y);
            ull d3a = pack2(z3.x, z3.x), d3b = pack2(z3.y, z3.y);

            #pragma unroll
            for (int p = 0; p < 5; p++) {
                ulonglong2 f = *(const ulonglong2*)(rk + p * 32 + h * 16);
                fma2(A[p * 4 + 0], d0a, f.x); fma2(A[p * 4 + 0], d0b, f.y);  // row0 re
                fma2(A[p * 4 + 1], d2a, f.x); fma2(A[p * 4 + 1], d2b, f.y);  // row0 im
                fma2(A[p * 4 + 2], d1a, f.x); fma2(A[p * 4 + 2], d1b, f.y);  // row1 re
                fma2(A[p * 4 + 3], d3a, f.x); fma2(A[p * 4 + 3], d3b, f.y);  // row1 im
            }
        }
    }

    __syncthreads();   // all cp.async landed & all warps done with ref -> overlay

    // lane partials: 8 warps x 20 ull rows, stride 33 (bank-conflict-free STS.64)
    // 160 * 33 * 8 = 42,240 B <= 72,192 B block smem (ring area is dead now)
    ull* red = (ull*)smem;
    #pragma unroll
    for (int i = 0; i < 20; i++)
        red[(w * 20 + i) * 33 + lane] = A[i];
    __syncthreads();

    // 80 tasks: (warp w2, class-pair p, row j) -> 2 outputs each
    if (tid < 80) {
        const int w2 = tid / 10;
        const int q  = tid % 10;
        const int p  = q >> 1;
        const int j  = q & 1;
        const int mRe = w2 * 20 + p * 4 + j * 2;
        ull sre = 0ull, sim = 0ull;
        #pragma unroll
        for (int x = 0; x < 32; x++) {
            add2(sre, red[mRe * 33 + x]);
            add2(sim, red[(mRe + 1) * 33 + x]);
        }
        float reL, reH, imL, imH;
        unpack2(sre, reL, reH);
        unpack2(sim, imL, imH);
        const size_t row = (size_t)rowBase0 + (size_t)w2 * 2 + (size_t)j;
        out[row * NCLS + 2 * p]     = reL * reL + imL * imL;
        out[row * NCLS + 2 * p + 1] = reH * reH + imH * imH;
    }
}

extern "C" void kernel_launch(void* const* d_in, const int* in_sizes, int n_in,
                              void* d_out, int out_size) {
    const float* zre   = (const float*)d_in[0];
    const float* zim   = (const float*)d_in[1];
    const float* canon = (const float*)d_in[2];
    float* out = (float*)d_out;

    cudaFuncSetAttribute(swap_test_kernel,
                         cudaFuncAttributeMaxDynamicSharedMemorySize, SMEM_TOTAL);

    ref_pack_kernel<<<NCLS / 2, 256>>>(canon);
    swap_test_kernel<<<NROWS / 16, 256, SMEM_TOTAL>>>(zre, zim, out);
}